// round 3
// baseline (speedup 1.0000x reference)
#include <cuda_runtime.h>
#include <cuda_bf16.h>
#include <cstdint>

// out[b,o,{re,im}] = complex(X) @ complex(W)^T (no conj), as ONE real GEMM:
//   C[M,N] = A[M,K] * B'[N,K]^T, M=N=K=4096
//   A = [Xre | Xim]
//   B'[n]      = [ Wre[n], -Wim[n] ]  (n<2048  -> out_re)
//   B'[n+2048] = [ Wim[n],  Wre[n] ]  (         -> out_im)
// Accuracy via 2-digit int8 Ozaki: per-row scale s=rowmax/16256,
//   round(v/s) = hi*128 + lo (|hi|<=127, |lo|<=64)
//   C ~= sA*sB*( (hiA.hiB)*16384 + (hiA.loB + loA.hiB)*128 )   [lo.lo dropped]
// int32 accumulation is exact; error is quantization-only (~1.5e-4).

static constexpr int M = 4096;
static constexpr int N = 4096;
static constexpr int K = 4096;
static constexpr int INF = 2048;
static constexpr int OUTF = 2048;

static constexpr int BM = 128;
static constexpr int BN = 128;
static constexpr int BK = 64;            // int8 k per stage
static constexpr int LDSB = BK + 16;     // 80B row stride (conflict-free ldmatrix)
static constexpr int TILE_B = BM * LDSB; // 10240 B per tile
static constexpr int STAGES = 3;
static constexpr int STAGE_B = 4 * TILE_B;            // Ahi,Alo,Bhi,Blo
static constexpr int SMEM_BYTES = STAGES * STAGE_B;   // 122880

// quantized operands + scales (device globals; runtime alloc forbidden)
__device__ int8_t g_Ahi[(size_t)M * K];
__device__ int8_t g_Alo[(size_t)M * K];
__device__ int8_t g_Bhi[(size_t)N * K];
__device__ int8_t g_Blo[(size_t)N * K];
__device__ float  g_sA[M];
__device__ float  g_sB[N];

// ---------------------------------------------------------------------------
// helpers
// ---------------------------------------------------------------------------
__device__ __forceinline__ void cp_async16(uint32_t saddr, const void* g) {
    asm volatile("cp.async.cg.shared.global [%0], [%1], 16;" :: "r"(saddr), "l"(g));
}
__device__ __forceinline__ void cp_commit() { asm volatile("cp.async.commit_group;"); }
__device__ __forceinline__ void cp_wait1()  { asm volatile("cp.async.wait_group 1;"); }

__device__ __forceinline__ void ldm_x4(uint32_t* r, uint32_t saddr) {
    asm volatile("ldmatrix.sync.aligned.m8n8.x4.shared.b16 {%0,%1,%2,%3}, [%4];"
                 : "=r"(r[0]), "=r"(r[1]), "=r"(r[2]), "=r"(r[3]) : "r"(saddr));
}
__device__ __forceinline__ void imma(int* c, const uint32_t* a, const uint32_t* b) {
    asm volatile("mma.sync.aligned.m16n8k32.row.col.s32.s8.s8.s32 "
                 "{%0,%1,%2,%3}, {%4,%5,%6,%7}, {%8,%9}, {%0,%1,%2,%3};"
                 : "+r"(c[0]), "+r"(c[1]), "+r"(c[2]), "+r"(c[3])
                 : "r"(a[0]), "r"(a[1]), "r"(a[2]), "r"(a[3]),
                   "r"(b[0]), "r"(b[1]));
}

__device__ __forceinline__ uint32_t pack4(int a, int b, int c, int d) {
    return (uint32_t)(uint8_t)(int8_t)a | ((uint32_t)(uint8_t)(int8_t)b << 8) |
           ((uint32_t)(uint8_t)(int8_t)c << 16) | ((uint32_t)(uint8_t)(int8_t)d << 24);
}

// ---------------------------------------------------------------------------
// quantization preps: one block per logical row, 256 threads, 16 elems/thread
// ---------------------------------------------------------------------------
__device__ __forceinline__ float block_rowmax(float local, float* red) {
    // warp reduce then cross-warp via smem
#pragma unroll
    for (int s = 16; s > 0; s >>= 1)
        local = fmaxf(local, __shfl_xor_sync(0xFFFFFFFF, local, s));
    int warp = threadIdx.x >> 5;
    if ((threadIdx.x & 31) == 0) red[warp] = local;
    __syncthreads();
    float m = red[threadIdx.x & 7];
#pragma unroll
    for (int s = 4; s > 0; s >>= 1)
        m = fmaxf(m, __shfl_xor_sync(0xFFFFFFFF, m, s));
    return m;
}

__device__ __forceinline__ void quant16(const float* v, float inv,
                                        int8_t* hi8, int8_t* lo8) {
#pragma unroll
    for (int i = 0; i < 16; i++) {
        float q  = rintf(v[i] * inv);
        float hf = rintf(q * 0.0078125f);   // q/128
        hi8[i] = (int8_t)(int)hf;
        lo8[i] = (int8_t)(int)(q - hf * 128.0f);
    }
}

__global__ void quantA(const float* __restrict__ xre, const float* __restrict__ xim) {
    __shared__ float red[8];
    const int row = blockIdx.x;
    const int t = threadIdx.x;
    float v[16];
#pragma unroll
    for (int c = 0; c < 4; c++) {
        int j = t * 16 + c * 4;                 // col in [0,4096)
        const float* src = (j < INF) ? (xre + (size_t)row * INF + j)
                                     : (xim + (size_t)row * INF + (j - INF));
        float4 f = *(const float4*)src;
        v[c * 4 + 0] = f.x; v[c * 4 + 1] = f.y; v[c * 4 + 2] = f.z; v[c * 4 + 3] = f.w;
    }
    float mx = 0.f;
#pragma unroll
    for (int i = 0; i < 16; i++) mx = fmaxf(mx, fabsf(v[i]));
    mx = block_rowmax(mx, red);
    float inv = (mx > 1e-30f) ? (16256.0f / mx) : 0.0f;
    if (t == 0) g_sA[row] = (mx > 1e-30f) ? (mx / 16256.0f) : 0.0f;

    int8_t h[16], l[16];
    quant16(v, inv, h, l);
    size_t base = (size_t)row * K + t * 16;
#pragma unroll
    for (int c = 0; c < 4; c++) {
        *(uint32_t*)(g_Ahi + base + c * 4) = pack4(h[c*4], h[c*4+1], h[c*4+2], h[c*4+3]);
        *(uint32_t*)(g_Alo + base + c * 4) = pack4(l[c*4], l[c*4+1], l[c*4+2], l[c*4+3]);
    }
}

// one block per output feature o; writes rows o ([wre | -wim]) and o+2048 ([wim | wre])
__global__ void quantB(const float* __restrict__ wre, const float* __restrict__ wim) {
    __shared__ float red[8];
    const int o = blockIdx.x;
    const int t = threadIdx.x;
    float v[16];
#pragma unroll
    for (int c = 0; c < 4; c++) {
        int j = t * 16 + c * 4;
        const float* src = (j < INF) ? (wre + (size_t)o * INF + j)
                                     : (wim + (size_t)o * INF + (j - INF));
        float4 f = *(const float4*)src;
        v[c * 4 + 0] = f.x; v[c * 4 + 1] = f.y; v[c * 4 + 2] = f.z; v[c * 4 + 3] = f.w;
    }
    float mx = 0.f;
#pragma unroll
    for (int i = 0; i < 16; i++) mx = fmaxf(mx, fabsf(v[i]));
    mx = block_rowmax(mx, red);
    float inv = (mx > 1e-30f) ? (16256.0f / mx) : 0.0f;
    if (t == 0) {
        float s = (mx > 1e-30f) ? (mx / 16256.0f) : 0.0f;
        g_sB[o] = s;
        g_sB[o + OUTF] = s;
    }

    int8_t h[16], l[16];
    quant16(v, inv, h, l);

    const int j0 = t * 16;
    const bool isRe = (j0 < INF);          // this thread's 16 vals are all wre or all wim
    // row o: [wre | -wim] ; row o+2048: [wim | wre]
    size_t rowA = (size_t)o * K + j0;                                   // same col
    size_t rowB = (size_t)(o + OUTF) * K + (isRe ? (j0 + INF) : (j0 - INF));
#pragma unroll
    for (int c = 0; c < 4; c++) {
        uint32_t ph = pack4(h[c*4], h[c*4+1], h[c*4+2], h[c*4+3]);
        uint32_t pl = pack4(l[c*4], l[c*4+1], l[c*4+2], l[c*4+3]);
        uint32_t nh = pack4(-h[c*4], -h[c*4+1], -h[c*4+2], -h[c*4+3]);
        uint32_t nl = pack4(-l[c*4], -l[c*4+1], -l[c*4+2], -l[c*4+3]);
        if (isRe) {
            *(uint32_t*)(g_Bhi + rowA + c * 4) = ph;   // wre in row o
            *(uint32_t*)(g_Blo + rowA + c * 4) = pl;
            *(uint32_t*)(g_Bhi + rowB + c * 4) = ph;   // wre in row o+2048 (k+2048)
            *(uint32_t*)(g_Blo + rowB + c * 4) = pl;
        } else {
            *(uint32_t*)(g_Bhi + rowA + c * 4) = nh;   // -wim in row o
            *(uint32_t*)(g_Blo + rowA + c * 4) = nl;
            *(uint32_t*)(g_Bhi + rowB + c * 4) = ph;   // wim in row o+2048 (k-2048)
            *(uint32_t*)(g_Blo + rowB + c * 4) = pl;
        }
    }
}

// ---------------------------------------------------------------------------
// int8 GEMM: 128x128 CTA, BK=64, 8 warps (2x4), warp tile 64x32.
// 3 digit products: hi*hi -> acc_hi ; hi*lo + lo*hi -> acc_mid.
// ---------------------------------------------------------------------------
__global__ void __launch_bounds__(256, 1) gemm_i8(float* __restrict__ out) {
    extern __shared__ __align__(128) int8_t smem[];

    const int tid  = threadIdx.x;
    const int lane = tid & 31;
    const int warp = tid >> 5;
    const int wm = warp >> 2;   // 0..1
    const int wn = warp & 3;    // 0..3
    const int bm0 = blockIdx.y * BM;
    const int bn0 = blockIdx.x * BN;

    int acc_hi[4][4][4], acc_mid[4][4][4];
#pragma unroll
    for (int i = 0; i < 4; i++)
#pragma unroll
        for (int j = 0; j < 4; j++)
#pragma unroll
            for (int q = 0; q < 4; q++) { acc_hi[i][j][q] = 0; acc_mid[i][j][q] = 0; }

    // 512 16B-chunks per 128x64B tile; thread t loads chunks t, t+256 of each tile
    auto load_stage = [&](int st, int k0) {
        int8_t* base = smem + st * STAGE_B;
#pragma unroll
        for (int rep = 0; rep < 2; rep++) {
            int ch  = tid + rep * 256;
            int row = ch >> 2;
            int cb  = (ch & 3) * 16;
            size_t gA = (size_t)(bm0 + row) * K + k0 + cb;
            size_t gB = (size_t)(bn0 + row) * K + k0 + cb;
            int so = row * LDSB + cb;
            cp_async16((uint32_t)__cvta_generic_to_shared(base + so),              g_Ahi + gA);
            cp_async16((uint32_t)__cvta_generic_to_shared(base + TILE_B + so),     g_Alo + gA);
            cp_async16((uint32_t)__cvta_generic_to_shared(base + 2 * TILE_B + so), g_Bhi + gB);
            cp_async16((uint32_t)__cvta_generic_to_shared(base + 3 * TILE_B + so), g_Blo + gB);
        }
    };

    load_stage(0, 0); cp_commit();
    load_stage(1, BK); cp_commit();

    const int NKT = K / BK;   // 64
#pragma unroll 1
    for (int kt = 0; kt < NKT; kt++) {
        cp_wait1();
        __syncthreads();
        if (kt + 2 < NKT) load_stage((kt + 2) % STAGES, (kt + 2) * BK);
        cp_commit();

        int8_t* base = smem + (kt % STAGES) * STAGE_B;
        int8_t* sAhi = base;
        int8_t* sAlo = base + TILE_B;
        int8_t* sBhi = base + 2 * TILE_B;
        int8_t* sBlo = base + 3 * TILE_B;

#pragma unroll
        for (int ks = 0; ks < 2; ks++) {
            const int kb = ks * 32;   // byte offset of this k32 step

            uint32_t ahi[4][4], alo[4][4];
            {
                int row = wm * 64 + (lane & 15);
                int cb  = kb + ((lane >> 4) << 4);
#pragma unroll
                for (int im = 0; im < 4; im++) {
                    int so = (row + im * 16) * LDSB + cb;
                    ldm_x4(ahi[im], (uint32_t)__cvta_generic_to_shared(sAhi + so));
                    ldm_x4(alo[im], (uint32_t)__cvta_generic_to_shared(sAlo + so));
                }
            }

            uint32_t bhi[4][2], blo[4][2];
            {
                int mset = lane >> 3;
                int nrow_in = (lane & 7) + ((mset >> 1) << 3);
                int cb = kb + ((mset & 1) << 4);
#pragma unroll
                for (int ip = 0; ip < 2; ip++) {
                    int nrow = wn * 32 + ip * 16 + nrow_in;
                    int so = nrow * LDSB + cb;
                    uint32_t r[4];
                    ldm_x4(r, (uint32_t)__cvta_generic_to_shared(sBhi + so));
                    bhi[ip * 2][0] = r[0]; bhi[ip * 2][1] = r[1];
                    bhi[ip * 2 + 1][0] = r[2]; bhi[ip * 2 + 1][1] = r[3];
                    ldm_x4(r, (uint32_t)__cvta_generic_to_shared(sBlo + so));
                    blo[ip * 2][0] = r[0]; blo[ip * 2][1] = r[1];
                    blo[ip * 2 + 1][0] = r[2]; blo[ip * 2 + 1][1] = r[3];
                }
            }

            // product-major order: consecutive mma hit different accumulators
#pragma unroll
            for (int im = 0; im < 4; im++)
#pragma unroll
                for (int in = 0; in < 4; in++) imma(acc_hi[im][in], ahi[im], bhi[in]);
#pragma unroll
            for (int im = 0; im < 4; im++)
#pragma unroll
                for (int in = 0; in < 4; in++) imma(acc_mid[im][in], ahi[im], blo[in]);
#pragma unroll
            for (int im = 0; im < 4; im++)
#pragma unroll
                for (int in = 0; in < 4; in++) imma(acc_mid[im][in], alo[im], bhi[in]);
        }
        __syncthreads();
    }

    // epilogue: C[m,n] = sA[m]*sB[n]*(hi*16384 + mid*128) -> out[m, n&2047, n>>11]
    const int gr = lane >> 2;
    const int gc = (lane & 3) << 1;

    float sa0[4], sa1[4];
#pragma unroll
    for (int im = 0; im < 4; im++) {
        int m0 = bm0 + wm * 64 + im * 16 + gr;
        sa0[im] = g_sA[m0];
        sa1[im] = g_sA[m0 + 8];
    }
    float sb0[4], sb1[4];
#pragma unroll
    for (int in = 0; in < 4; in++) {
        int n0 = bn0 + wn * 32 + in * 8 + gc;
        sb0[in] = g_sB[n0];
        sb1[in] = g_sB[n0 + 1];
    }

#pragma unroll
    for (int im = 0; im < 4; im++) {
#pragma unroll
        for (int in = 0; in < 4; in++) {
            int m0 = bm0 + wm * 64 + im * 16 + gr;
            int n0 = bn0 + wn * 32 + in * 8 + gc;
            int c = n0 >> 11;
            int o = n0 & (OUTF - 1);
            float v0 = sa0[im] * sb0[in] *
                       fmaf((float)acc_hi[im][in][0], 16384.f, (float)acc_mid[im][in][0] * 128.f);
            float v1 = sa0[im] * sb1[in] *
                       fmaf((float)acc_hi[im][in][1], 16384.f, (float)acc_mid[im][in][1] * 128.f);
            float v2 = sa1[im] * sb0[in] *
                       fmaf((float)acc_hi[im][in][2], 16384.f, (float)acc_mid[im][in][2] * 128.f);
            float v3 = sa1[im] * sb1[in] *
                       fmaf((float)acc_hi[im][in][3], 16384.f, (float)acc_mid[im][in][3] * 128.f);
            out[((size_t)m0 * OUTF + o) * 2 + c]           = v0;
            out[((size_t)m0 * OUTF + o + 1) * 2 + c]       = v1;
            out[((size_t)(m0 + 8) * OUTF + o) * 2 + c]     = v2;
            out[((size_t)(m0 + 8) * OUTF + o + 1) * 2 + c] = v3;
        }
    }
}

// ---------------------------------------------------------------------------
extern "C" void kernel_launch(void* const* d_in, const int* in_sizes, int n_in,
                              void* d_out, int out_size) {
    const float* x_re = (const float*)d_in[0];
    const float* x_im = (const float*)d_in[1];
    const float* w_re = (const float*)d_in[2];
    const float* w_im = (const float*)d_in[3];
    float* out = (float*)d_out;

    cudaFuncSetAttribute(gemm_i8, cudaFuncAttributeMaxDynamicSharedMemorySize, SMEM_BYTES);

    quantA<<<M, 256>>>(x_re, x_im);
    quantB<<<OUTF, 256>>>(w_re, w_im);

    dim3 grid(N / BN, M / BM);   // 32 x 32
    gemm_i8<<<grid, 256, SMEM_BYTES>>>(out);
}

// round 4
// speedup vs baseline: 2.6297x; 2.6297x over previous
#include <cuda_runtime.h>
#include <cuda_bf16.h>
#include <cstdint>

// out[b,o,{re,im}] = complex(X) @ complex(W)^T (no conj), as ONE real GEMM:
//   C[M,N] = A[M,K] * B'[N,K]^T, M=N=K=4096
//   A = [Xre | Xim]
//   B'[n]      = [ Wre[n], -Wim[n] ]  (n<2048  -> out_re)
//   B'[n+2048] = [ Wim[n],  Wre[n] ]  (         -> out_im)
// fp32 accuracy via 3-term bf16 split: C = Ah*Bh + Ah*Bl + Al*Bh (fp32 accum).
// vs R1: product-major MMA order (no accumulator RAW chains), 2 CTAs/SM,
// fused prep (1 launch).

static constexpr int M = 4096;
static constexpr int N = 4096;
static constexpr int K = 4096;
static constexpr int INF = 2048;
static constexpr int OUTF = 2048;

static constexpr int BM = 128;
static constexpr int BN = 128;
static constexpr int BK = 32;
static constexpr int LDS = BK + 8;        // 40 bf16 = 80B row (conflict-free ldmatrix)
static constexpr int TILE_A = BM * LDS;   // 5120 elems
static constexpr int TILE_B = BN * LDS;
static constexpr int SMEM_BYTES = (2 * TILE_A * 2 + 2 * TILE_B * 2) * 2; // 81920 B

__device__ __nv_bfloat16 g_Ahi[(size_t)M * K];
__device__ __nv_bfloat16 g_Alo[(size_t)M * K];
__device__ __nv_bfloat16 g_Bhi[(size_t)N * K];
__device__ __nv_bfloat16 g_Blo[(size_t)N * K];

// ---------------------------------------------------------------------------
// Fused prep: one launch builds all split operands.
//   idx in [0, M*K)        -> A = [Xre | Xim]
//   idx in [M*K, M*K+N*K)  -> B' rows per the mapping above
// ---------------------------------------------------------------------------
__global__ void prep_all(const float* __restrict__ xre, const float* __restrict__ xim,
                         const float* __restrict__ wre, const float* __restrict__ wim) {
    size_t idx = (size_t)blockIdx.x * blockDim.x + threadIdx.x;
    if (idx < (size_t)M * K) {
        int k = (int)(idx & (K - 1));
        int b = (int)(idx >> 12);
        float v = (k < INF) ? xre[(size_t)b * INF + k] : xim[(size_t)b * INF + (k - INF)];
        __nv_bfloat16 hi = __float2bfloat16(v);
        g_Ahi[idx] = hi;
        g_Alo[idx] = __float2bfloat16(v - __bfloat162float(hi));
    } else {
        size_t j = idx - (size_t)M * K;
        int k = (int)(j & (K - 1));
        int n = (int)(j >> 12);
        float v;
        if (n < OUTF) {
            v = (k < INF) ? wre[(size_t)n * INF + k] : -wim[(size_t)n * INF + (k - INF)];
        } else {
            int o = n - OUTF;
            v = (k < INF) ? wim[(size_t)o * INF + k] : wre[(size_t)o * INF + (k - INF)];
        }
        __nv_bfloat16 hi = __float2bfloat16(v);
        g_Bhi[j] = hi;
        g_Blo[j] = __float2bfloat16(v - __bfloat162float(hi));
    }
}

// ---------------------------------------------------------------------------
// MMA / ldmatrix / cp.async helpers
// ---------------------------------------------------------------------------
__device__ __forceinline__ void cp_async16(uint32_t saddr, const void* g) {
    asm volatile("cp.async.cg.shared.global [%0], [%1], 16;" :: "r"(saddr), "l"(g));
}
__device__ __forceinline__ void cp_commit() { asm volatile("cp.async.commit_group;"); }
__device__ __forceinline__ void cp_wait1()  { asm volatile("cp.async.wait_group 1;"); }

__device__ __forceinline__ void ldm_x4(uint32_t* r, uint32_t saddr) {
    asm volatile("ldmatrix.sync.aligned.m8n8.x4.shared.b16 {%0,%1,%2,%3}, [%4];"
                 : "=r"(r[0]), "=r"(r[1]), "=r"(r[2]), "=r"(r[3]) : "r"(saddr));
}
__device__ __forceinline__ void mma16816(float* c, const uint32_t* a, const uint32_t* b) {
    asm volatile("mma.sync.aligned.m16n8k16.row.col.f32.bf16.bf16.f32 "
                 "{%0,%1,%2,%3}, {%4,%5,%6,%7}, {%8,%9}, {%0,%1,%2,%3};"
                 : "+f"(c[0]), "+f"(c[1]), "+f"(c[2]), "+f"(c[3])
                 : "r"(a[0]), "r"(a[1]), "r"(a[2]), "r"(a[3]),
                   "r"(b[0]), "r"(b[1]));
}

// ---------------------------------------------------------------------------
// GEMM: 128x128 CTA, BK=32, 8 warps (2x4), warp tile 64x32, 2 CTAs/SM.
// Product-major split products: P1 hi*hi, P2 hi*lo, P3 lo*hi (alo loaded late
// so its registers reuse ahi's — keeps the kernel under 128 regs).
// ---------------------------------------------------------------------------
__global__ void __launch_bounds__(256, 2) gemm_split3(float* __restrict__ out) {
    extern __shared__ __align__(16) __nv_bfloat16 smem[];
    __nv_bfloat16* sAhi = smem;
    __nv_bfloat16* sAlo = sAhi + 2 * TILE_A;
    __nv_bfloat16* sBhi = sAlo + 2 * TILE_A;
    __nv_bfloat16* sBlo = sBhi + 2 * TILE_B;

    const int tid  = threadIdx.x;
    const int lane = tid & 31;
    const int warp = tid >> 5;
    const int wm = warp >> 2;     // 0..1
    const int wn = warp & 3;      // 0..3
    const int bm0 = blockIdx.y * BM;
    const int bn0 = blockIdx.x * BN;

    float acc[4][4][4];
#pragma unroll
    for (int i = 0; i < 4; i++)
#pragma unroll
        for (int j = 0; j < 4; j++)
#pragma unroll
            for (int q = 0; q < 4; q++) acc[i][j][q] = 0.f;

    auto load_tile = [&](int buf, int k0) {
#pragma unroll
        for (int rep = 0; rep < 2; rep++) {
            int ch  = tid + rep * 256;
            int row = ch >> 2;
            int col = (ch & 3) * 8;
            size_t goffA = (size_t)(bm0 + row) * K + k0 + col;
            size_t goffB = (size_t)(bn0 + row) * K + k0 + col;
            int soff = buf * TILE_A + row * LDS + col;
            cp_async16((uint32_t)__cvta_generic_to_shared(sAhi + soff), g_Ahi + goffA);
            cp_async16((uint32_t)__cvta_generic_to_shared(sAlo + soff), g_Alo + goffA);
            cp_async16((uint32_t)__cvta_generic_to_shared(sBhi + soff), g_Bhi + goffB);
            cp_async16((uint32_t)__cvta_generic_to_shared(sBlo + soff), g_Blo + goffB);
        }
    };

    load_tile(0, 0);
    cp_commit();

    const int NKT = K / BK;   // 128
#pragma unroll 1
    for (int kt = 0; kt < NKT; kt++) {
        int cur = kt & 1;
        if (kt + 1 < NKT) load_tile(cur ^ 1, (kt + 1) * BK);
        cp_commit();
        cp_wait1();
        __syncthreads();

#pragma unroll
        for (int ks = 0; ks < 2; ks++) {
            const int kk = ks * 16;

            // A hi fragments
            uint32_t ahi[4][4];
            const int arow = wm * 64 + (lane & 15);
            const int acol = kk + ((lane >> 4) << 3);
#pragma unroll
            for (int im = 0; im < 4; im++) {
                int soff = cur * TILE_A + (arow + im * 16) * LDS + acol;
                ldm_x4(ahi[im], (uint32_t)__cvta_generic_to_shared(sAhi + soff));
            }

            // B hi/lo fragments
            uint32_t bhi[4][2], blo[4][2];
            {
                int mset = lane >> 3;
                int nrow_in = (lane & 7) + ((mset >> 1) << 3);
                int col = kk + ((mset & 1) << 3);
#pragma unroll
                for (int ip = 0; ip < 2; ip++) {
                    int nrow = wn * 32 + ip * 16 + nrow_in;
                    int soff = cur * TILE_B + nrow * LDS + col;
                    uint32_t r[4];
                    ldm_x4(r, (uint32_t)__cvta_generic_to_shared(sBhi + soff));
                    bhi[ip * 2][0] = r[0]; bhi[ip * 2][1] = r[1];
                    bhi[ip * 2 + 1][0] = r[2]; bhi[ip * 2 + 1][1] = r[3];
                    ldm_x4(r, (uint32_t)__cvta_generic_to_shared(sBlo + soff));
                    blo[ip * 2][0] = r[0]; blo[ip * 2][1] = r[1];
                    blo[ip * 2 + 1][0] = r[2]; blo[ip * 2 + 1][1] = r[3];
                }
            }

            // P1: hi*hi  (16 independent accumulators back-to-back)
#pragma unroll
            for (int im = 0; im < 4; im++)
#pragma unroll
                for (int in = 0; in < 4; in++) mma16816(acc[im][in], ahi[im], bhi[in]);
            // P2: hi*lo
#pragma unroll
            for (int im = 0; im < 4; im++)
#pragma unroll
                for (int in = 0; in < 4; in++) mma16816(acc[im][in], ahi[im], blo[in]);

            // A lo fragments (after ahi is dead -> register reuse)
            uint32_t alo[4][4];
#pragma unroll
            for (int im = 0; im < 4; im++) {
                int soff = cur * TILE_A + (arow + im * 16) * LDS + acol;
                ldm_x4(alo[im], (uint32_t)__cvta_generic_to_shared(sAlo + soff));
            }
            // P3: lo*hi
#pragma unroll
            for (int im = 0; im < 4; im++)
#pragma unroll
                for (int in = 0; in < 4; in++) mma16816(acc[im][in], alo[im], bhi[in]);
        }
        __syncthreads();
    }

    // Epilogue: C[m, n] -> out[m, n & 2047, n >> 11]
    const int gr = lane >> 2;
    const int gc = (lane & 3) << 1;
#pragma unroll
    for (int im = 0; im < 4; im++) {
#pragma unroll
        for (int in = 0; in < 4; in++) {
            int m0 = bm0 + wm * 64 + im * 16 + gr;
            int n0 = bn0 + wn * 32 + in * 8 + gc;
            int c = n0 >> 11;
            int o = n0 & (OUTF - 1);
            out[((size_t)m0 * OUTF + o) * 2 + c]           = acc[im][in][0];
            out[((size_t)m0 * OUTF + o + 1) * 2 + c]       = acc[im][in][1];
            out[((size_t)(m0 + 8) * OUTF + o) * 2 + c]     = acc[im][in][2];
            out[((size_t)(m0 + 8) * OUTF + o + 1) * 2 + c] = acc[im][in][3];
        }
    }
}

// ---------------------------------------------------------------------------
extern "C" void kernel_launch(void* const* d_in, const int* in_sizes, int n_in,
                              void* d_out, int out_size) {
    const float* x_re = (const float*)d_in[0];
    const float* x_im = (const float*)d_in[1];
    const float* w_re = (const float*)d_in[2];
    const float* w_im = (const float*)d_in[3];
    float* out = (float*)d_out;

    cudaFuncSetAttribute(gemm_split3, cudaFuncAttributeMaxDynamicSharedMemorySize,
                         SMEM_BYTES);

    size_t total = (size_t)M * K + (size_t)N * K;   // 32M elems
    prep_all<<<(unsigned)(total / 256), 256>>>(x_re, x_im, w_re, w_im);

    dim3 grid(N / BN, M / BM);
    gemm_split3<<<grid, 256, SMEM_BYTES>>>(out);
}

// round 5
// speedup vs baseline: 6.2598x; 2.3805x over previous
#include <cuda_runtime.h>
#include <cuda_fp16.h>
#include <cstdint>

// out[b,o,{re,im}] = complex(X) @ complex(W)^T (no conj), as ONE real GEMM:
//   C[M,N] = A[M,K] * B'[N,K]^T, M=N=K=4096
//   A = [Xre | Xim]
//   B'[n]      = [ Wre[n], -Wim[n] ]  (n<2048  -> out_re)
//   B'[n+2048] = [ Wim[n],  Wre[n] ]  (         -> out_im)
// Single fp16 product with fp32 accumulation. fp16 11-bit mantissa =>
// norm-relative output error ~4e-4 < 1e-3 threshold. 3x fewer MMAs than
// the bf16 3-term split.

static constexpr int M = 4096;
static constexpr int N = 4096;
static constexpr int K = 4096;
static constexpr int INF = 2048;
static constexpr int OUTF = 2048;

static constexpr int BM = 128;
static constexpr int BN = 128;
static constexpr int BK = 64;
static constexpr int LDS = BK + 8;        // 72 fp16 = 144B row stride (conflict-free)
static constexpr int TILE = BM * LDS;     // 9216 elems per tile buffer
static constexpr int SMEM_BYTES = 2 * 2 * TILE * 2;  // A+B, double buffered: 73728 B

__device__ __half g_A[(size_t)M * K];
__device__ __half g_B[(size_t)N * K];

// ---------------------------------------------------------------------------
// Fused prep: build A = [Xre|Xim], B' per mapping, in fp16.
// ---------------------------------------------------------------------------
__global__ void prep_all(const float* __restrict__ xre, const float* __restrict__ xim,
                         const float* __restrict__ wre, const float* __restrict__ wim) {
    size_t idx = (size_t)blockIdx.x * blockDim.x + threadIdx.x;
    if (idx < (size_t)M * K) {
        int k = (int)(idx & (K - 1));
        int b = (int)(idx >> 12);
        float v = (k < INF) ? xre[(size_t)b * INF + k] : xim[(size_t)b * INF + (k - INF)];
        g_A[idx] = __float2half(v);
    } else {
        size_t j = idx - (size_t)M * K;
        int k = (int)(j & (K - 1));
        int n = (int)(j >> 12);
        float v;
        if (n < OUTF) {
            v = (k < INF) ? wre[(size_t)n * INF + k] : -wim[(size_t)n * INF + (k - INF)];
        } else {
            int o = n - OUTF;
            v = (k < INF) ? wim[(size_t)o * INF + k] : wre[(size_t)o * INF + (k - INF)];
        }
        g_B[j] = __float2half(v);
    }
}

// ---------------------------------------------------------------------------
// helpers
// ---------------------------------------------------------------------------
__device__ __forceinline__ void cp_async16(uint32_t saddr, const void* g) {
    asm volatile("cp.async.cg.shared.global [%0], [%1], 16;" :: "r"(saddr), "l"(g));
}
__device__ __forceinline__ void cp_commit() { asm volatile("cp.async.commit_group;"); }
__device__ __forceinline__ void cp_wait1()  { asm volatile("cp.async.wait_group 1;"); }

__device__ __forceinline__ void ldm_x4(uint32_t* r, uint32_t saddr) {
    asm volatile("ldmatrix.sync.aligned.m8n8.x4.shared.b16 {%0,%1,%2,%3}, [%4];"
                 : "=r"(r[0]), "=r"(r[1]), "=r"(r[2]), "=r"(r[3]) : "r"(saddr));
}
__device__ __forceinline__ void mma16816(float* c, const uint32_t* a, const uint32_t* b) {
    asm volatile("mma.sync.aligned.m16n8k16.row.col.f32.f16.f16.f32 "
                 "{%0,%1,%2,%3}, {%4,%5,%6,%7}, {%8,%9}, {%0,%1,%2,%3};"
                 : "+f"(c[0]), "+f"(c[1]), "+f"(c[2]), "+f"(c[3])
                 : "r"(a[0]), "r"(a[1]), "r"(a[2]), "r"(a[3]),
                   "r"(b[0]), "r"(b[1]));
}

// ---------------------------------------------------------------------------
// GEMM: 128x128 CTA, BK=64, 8 warps (2x4), warp tile 64x32, 2 CTAs/SM.
// ---------------------------------------------------------------------------
__global__ void __launch_bounds__(256, 2) gemm_f16(float* __restrict__ out) {
    extern __shared__ __align__(16) __half smem[];
    __half* sA = smem;                 // 2 * TILE
    __half* sB = smem + 2 * TILE;      // 2 * TILE

    const int tid  = threadIdx.x;
    const int lane = tid & 31;
    const int warp = tid >> 5;
    const int wm = warp >> 2;     // 0..1
    const int wn = warp & 3;      // 0..3
    const int bm0 = blockIdx.y * BM;
    const int bn0 = blockIdx.x * BN;

    float acc[4][4][4];
#pragma unroll
    for (int i = 0; i < 4; i++)
#pragma unroll
        for (int j = 0; j < 4; j++)
#pragma unroll
            for (int q = 0; q < 4; q++) acc[i][j][q] = 0.f;

    // per stage: 128 rows x 4 chunks(16B)=8 fp16... actually 64 fp16 = 4 chunks?
    // 64 fp16 = 128B = 8 x 16B chunks. 128 rows * 8 = 1024 chunks per tile.
    auto load_tile = [&](int buf, int k0) {
#pragma unroll
        for (int rep = 0; rep < 4; rep++) {
            int ch  = tid + rep * 256;        // 0..1023
            int row = ch >> 3;
            int col = (ch & 7) * 8;           // fp16 elems
            size_t gA = (size_t)(bm0 + row) * K + k0 + col;
            size_t gB = (size_t)(bn0 + row) * K + k0 + col;
            int soff = buf * TILE + row * LDS + col;
            cp_async16((uint32_t)__cvta_generic_to_shared(sA + soff), g_A + gA);
            cp_async16((uint32_t)__cvta_generic_to_shared(sB + soff), g_B + gB);
        }
    };

    load_tile(0, 0);
    cp_commit();

    const int NKT = K / BK;   // 64
#pragma unroll 1
    for (int kt = 0; kt < NKT; kt++) {
        int cur = kt & 1;
        if (kt + 1 < NKT) load_tile(cur ^ 1, (kt + 1) * BK);
        cp_commit();
        cp_wait1();
        __syncthreads();

#pragma unroll
        for (int ks = 0; ks < 4; ks++) {
            const int kk = ks * 16;

            uint32_t af[4][4];
            const int arow = wm * 64 + (lane & 15);
            const int acol = kk + ((lane >> 4) << 3);
#pragma unroll
            for (int im = 0; im < 4; im++) {
                int soff = cur * TILE + (arow + im * 16) * LDS + acol;
                ldm_x4(af[im], (uint32_t)__cvta_generic_to_shared(sA + soff));
            }

            uint32_t bf[4][2];
            {
                int mset = lane >> 3;
                int nrow_in = (lane & 7) + ((mset >> 1) << 3);
                int col = kk + ((mset & 1) << 3);
#pragma unroll
                for (int ip = 0; ip < 2; ip++) {
                    int nrow = wn * 32 + ip * 16 + nrow_in;
                    int soff = cur * TILE + nrow * LDS + col;
                    uint32_t r[4];
                    ldm_x4(r, (uint32_t)__cvta_generic_to_shared(sB + soff));
                    bf[ip * 2][0] = r[0]; bf[ip * 2][1] = r[1];
                    bf[ip * 2 + 1][0] = r[2]; bf[ip * 2 + 1][1] = r[3];
                }
            }

#pragma unroll
            for (int im = 0; im < 4; im++)
#pragma unroll
                for (int in = 0; in < 4; in++) mma16816(acc[im][in], af[im], bf[in]);
        }
        __syncthreads();
    }

    // Epilogue: C[m, n] -> out[m, n & 2047, n >> 11]
    const int gr = lane >> 2;
    const int gc = (lane & 3) << 1;
#pragma unroll
    for (int im = 0; im < 4; im++) {
#pragma unroll
        for (int in = 0; in < 4; in++) {
            int m0 = bm0 + wm * 64 + im * 16 + gr;
            int n0 = bn0 + wn * 32 + in * 8 + gc;
            int c = n0 >> 11;
            int o = n0 & (OUTF - 1);
            out[((size_t)m0 * OUTF + o) * 2 + c]           = acc[im][in][0];
            out[((size_t)m0 * OUTF + o + 1) * 2 + c]       = acc[im][in][1];
            out[((size_t)(m0 + 8) * OUTF + o) * 2 + c]     = acc[im][in][2];
            out[((size_t)(m0 + 8) * OUTF + o + 1) * 2 + c] = acc[im][in][3];
        }
    }
}

// ---------------------------------------------------------------------------
extern "C" void kernel_launch(void* const* d_in, const int* in_sizes, int n_in,
                              void* d_out, int out_size) {
    const float* x_re = (const float*)d_in[0];
    const float* x_im = (const float*)d_in[1];
    const float* w_re = (const float*)d_in[2];
    const float* w_im = (const float*)d_in[3];
    float* out = (float*)d_out;

    cudaFuncSetAttribute(gemm_f16, cudaFuncAttributeMaxDynamicSharedMemorySize,
                         SMEM_BYTES);

    size_t total = (size_t)M * K + (size_t)N * K;   // 32M elems
    prep_all<<<(unsigned)(total / 256), 256>>>(x_re, x_im, w_re, w_im);

    dim3 grid(N / BN, M / BM);
    gemm_f16<<<grid, 256, SMEM_BYTES>>>(out);
}

// round 6
// speedup vs baseline: 7.3948x; 1.1813x over previous
#include <cuda_runtime.h>
#include <cuda_fp16.h>
#include <cstdint>

// out[b,o,{re,im}] = complex(X) @ complex(W)^T (no conj), as ONE real GEMM:
//   C[M,N] = A[M,K] * B'[N,K]^T, M=N=K=4096
//   A = [Xre | Xim]
//   B'[n]      = [ Wre[n], -Wim[n] ]  (n<2048  -> out_re)
//   B'[n+2048] = [ Wim[n],  Wre[n] ]  (         -> out_im)
// Single fp16 product with fp32 accumulation (rel_err ~3e-4 < 1e-3).
// R6: vectorized prep (8 elem/thread), 3-stage cp.async ring.

static constexpr int M = 4096;
static constexpr int N = 4096;
static constexpr int K = 4096;
static constexpr int INF = 2048;
static constexpr int OUTF = 2048;

static constexpr int BM = 128;
static constexpr int BN = 128;
static constexpr int BK = 64;
static constexpr int LDS = BK + 8;        // 72 fp16 = 144B row stride (conflict-free)
static constexpr int TILE = BM * LDS;     // 9216 elems per tile
static constexpr int STAGES = 3;
static constexpr int STAGE_ELEMS = 2 * TILE;               // A tile + B tile
static constexpr int SMEM_BYTES = STAGES * STAGE_ELEMS * 2; // 110592 B

__device__ __half g_A[(size_t)M * K];
__device__ __half g_B[(size_t)N * K];

// ---------------------------------------------------------------------------
// Vectorized prep: 8 elems per thread (two float4 loads -> one uint4 store).
// idx8 < M*K -> A ; else -> B'.
// ---------------------------------------------------------------------------
__global__ void prep_all(const float* __restrict__ xre, const float* __restrict__ xim,
                         const float* __restrict__ wre, const float* __restrict__ wim) {
    size_t idx8 = ((size_t)blockIdx.x * blockDim.x + threadIdx.x) * 8;
    float4 f0, f1;
    float sgn = 1.0f;
    __half* dst;

    if (idx8 < (size_t)M * K) {
        int k = (int)(idx8 & (K - 1));
        int b = (int)(idx8 >> 12);
        const float* src = (k < INF) ? (xre + (size_t)b * INF + k)
                                     : (xim + (size_t)b * INF + (k - INF));
        f0 = *(const float4*)src;
        f1 = *(const float4*)(src + 4);
        dst = g_A + idx8;
    } else {
        size_t j = idx8 - (size_t)M * K;
        int k = (int)(j & (K - 1));
        int n = (int)(j >> 12);
        const float* src;
        if (n < OUTF) {
            if (k < INF) { src = wre + (size_t)n * INF + k; }
            else         { src = wim + (size_t)n * INF + (k - INF); sgn = -1.0f; }
        } else {
            int o = n - OUTF;
            src = (k < INF) ? (wim + (size_t)o * INF + k)
                            : (wre + (size_t)o * INF + (k - INF));
        }
        f0 = *(const float4*)src;
        f1 = *(const float4*)(src + 4);
        dst = g_B + j;
    }

    __half h[8];
    h[0] = __float2half(sgn * f0.x); h[1] = __float2half(sgn * f0.y);
    h[2] = __float2half(sgn * f0.z); h[3] = __float2half(sgn * f0.w);
    h[4] = __float2half(sgn * f1.x); h[5] = __float2half(sgn * f1.y);
    h[6] = __float2half(sgn * f1.z); h[7] = __float2half(sgn * f1.w);
    *(uint4*)dst = *(const uint4*)h;
}

// ---------------------------------------------------------------------------
// helpers
// ---------------------------------------------------------------------------
__device__ __forceinline__ void cp_async16(uint32_t saddr, const void* g) {
    asm volatile("cp.async.cg.shared.global [%0], [%1], 16;" :: "r"(saddr), "l"(g));
}
__device__ __forceinline__ void cp_commit() { asm volatile("cp.async.commit_group;"); }
__device__ __forceinline__ void cp_wait1()  { asm volatile("cp.async.wait_group 1;"); }

__device__ __forceinline__ void ldm_x4(uint32_t* r, uint32_t saddr) {
    asm volatile("ldmatrix.sync.aligned.m8n8.x4.shared.b16 {%0,%1,%2,%3}, [%4];"
                 : "=r"(r[0]), "=r"(r[1]), "=r"(r[2]), "=r"(r[3]) : "r"(saddr));
}
__device__ __forceinline__ void mma16816(float* c, const uint32_t* a, const uint32_t* b) {
    asm volatile("mma.sync.aligned.m16n8k16.row.col.f32.f16.f16.f32 "
                 "{%0,%1,%2,%3}, {%4,%5,%6,%7}, {%8,%9}, {%0,%1,%2,%3};"
                 : "+f"(c[0]), "+f"(c[1]), "+f"(c[2]), "+f"(c[3])
                 : "r"(a[0]), "r"(a[1]), "r"(a[2]), "r"(a[3]),
                   "r"(b[0]), "r"(b[1]));
}

// ---------------------------------------------------------------------------
// GEMM: 128x128 CTA, BK=64, 8 warps (2x4), warp tile 64x32, 2 CTAs/SM,
// 3-stage cp.async ring.
// ---------------------------------------------------------------------------
__global__ void __launch_bounds__(256, 2) gemm_f16(float* __restrict__ out) {
    extern __shared__ __align__(16) __half smem[];

    const int tid  = threadIdx.x;
    const int lane = tid & 31;
    const int warp = tid >> 5;
    const int wm = warp >> 2;     // 0..1
    const int wn = warp & 3;      // 0..3
    const int bm0 = blockIdx.y * BM;
    const int bn0 = blockIdx.x * BN;

    float acc[4][4][4];
#pragma unroll
    for (int i = 0; i < 4; i++)
#pragma unroll
        for (int j = 0; j < 4; j++)
#pragma unroll
            for (int q = 0; q < 4; q++) acc[i][j][q] = 0.f;

    // 1024 16B-chunks per (A+B) stage half; thread t loads 4 chunks of A, 4 of B.
    auto load_tile = [&](int st, int k0) {
        __half* sA = smem + st * STAGE_ELEMS;
        __half* sB = sA + TILE;
#pragma unroll
        for (int rep = 0; rep < 4; rep++) {
            int ch  = tid + rep * 256;        // 0..1023
            int row = ch >> 3;
            int col = (ch & 7) * 8;           // fp16 elems
            size_t gA = (size_t)(bm0 + row) * K + k0 + col;
            size_t gB = (size_t)(bn0 + row) * K + k0 + col;
            int soff = row * LDS + col;
            cp_async16((uint32_t)__cvta_generic_to_shared(sA + soff), g_A + gA);
            cp_async16((uint32_t)__cvta_generic_to_shared(sB + soff), g_B + gB);
        }
    };

    load_tile(0, 0);       cp_commit();
    load_tile(1, BK);      cp_commit();

    const int NKT = K / BK;   // 64
#pragma unroll 1
    for (int kt = 0; kt < NKT; kt++) {
        cp_wait1();              // stage kt resident
        __syncthreads();

        // prefetch stage kt+2 into the buffer freed at iter kt-1
        if (kt + 2 < NKT) load_tile((kt + 2) % STAGES, (kt + 2) * BK);
        cp_commit();

        const int cur = kt % STAGES;
        const __half* sA = smem + cur * STAGE_ELEMS;
        const __half* sB = sA + TILE;

#pragma unroll
        for (int ks = 0; ks < 4; ks++) {
            const int kk = ks * 16;

            uint32_t af[4][4];
            const int arow = wm * 64 + (lane & 15);
            const int acol = kk + ((lane >> 4) << 3);
#pragma unroll
            for (int im = 0; im < 4; im++) {
                int soff = (arow + im * 16) * LDS + acol;
                ldm_x4(af[im], (uint32_t)__cvta_generic_to_shared(sA + soff));
            }

            uint32_t bf[4][2];
            {
                int mset = lane >> 3;
                int nrow_in = (lane & 7) + ((mset >> 1) << 3);
                int col = kk + ((mset & 1) << 3);
#pragma unroll
                for (int ip = 0; ip < 2; ip++) {
                    int nrow = wn * 32 + ip * 16 + nrow_in;
                    int soff = nrow * LDS + col;
                    uint32_t r[4];
                    ldm_x4(r, (uint32_t)__cvta_generic_to_shared(sB + soff));
                    bf[ip * 2][0] = r[0]; bf[ip * 2][1] = r[1];
                    bf[ip * 2 + 1][0] = r[2]; bf[ip * 2 + 1][1] = r[3];
                }
            }

#pragma unroll
            for (int im = 0; im < 4; im++)
#pragma unroll
                for (int in = 0; in < 4; in++) mma16816(acc[im][in], af[im], bf[in]);
        }
        __syncthreads();
    }

    // Epilogue: C[m, n] -> out[m, n & 2047, n >> 11]
    const int gr = lane >> 2;
    const int gc = (lane & 3) << 1;
#pragma unroll
    for (int im = 0; im < 4; im++) {
#pragma unroll
        for (int in = 0; in < 4; in++) {
            int m0 = bm0 + wm * 64 + im * 16 + gr;
            int n0 = bn0 + wn * 32 + in * 8 + gc;
            int c = n0 >> 11;
            int o = n0 & (OUTF - 1);
            out[((size_t)m0 * OUTF + o) * 2 + c]           = acc[im][in][0];
            out[((size_t)m0 * OUTF + o + 1) * 2 + c]       = acc[im][in][1];
            out[((size_t)(m0 + 8) * OUTF + o) * 2 + c]     = acc[im][in][2];
            out[((size_t)(m0 + 8) * OUTF + o + 1) * 2 + c] = acc[im][in][3];
        }
    }
}

// ---------------------------------------------------------------------------
extern "C" void kernel_launch(void* const* d_in, const int* in_sizes, int n_in,
                              void* d_out, int out_size) {
    const float* x_re = (const float*)d_in[0];
    const float* x_im = (const float*)d_in[1];
    const float* w_re = (const float*)d_in[2];
    const float* w_im = (const float*)d_in[3];
    float* out = (float*)d_out;

    cudaFuncSetAttribute(gemm_f16, cudaFuncAttributeMaxDynamicSharedMemorySize,
                         SMEM_BYTES);

    size_t total8 = ((size_t)M * K + (size_t)N * K) / 8;   // 4M threads
    prep_all<<<(unsigned)(total8 / 256), 256>>>(x_re, x_im, w_re, w_im);

    dim3 grid(N / BN, M / BM);
    gemm_f16<<<grid, 256, SMEM_BYTES>>>(out);
}

// round 7
// speedup vs baseline: 7.7010x; 1.0414x over previous
#include <cuda_runtime.h>
#include <cuda_fp16.h>
#include <cstdint>

// out[b,o,{re,im}] = complex(X) @ complex(W)^T (no conj), as ONE real GEMM:
//   C[M,N] = A[M,K] * B'[N,K]^T, M=N=K=4096
//   A = [Xre | Xim]
//   B'[n]      = [ Wre[n], -Wim[n] ]  (n<2048  -> out_re)
//   B'[n+2048] = [ Wim[n],  Wre[n] ]  (         -> out_im)
// Single fp16 product with fp32 accumulation (rel_err ~3e-4 < 1e-3).
// R7: 4 warps x (64x64) warp tiles (halved ldmatrix/MMA issue overhead),
//     128-thread CTAs, 2 CTAs/SM, 3-stage cp.async ring.

static constexpr int M = 4096;
static constexpr int N = 4096;
static constexpr int K = 4096;
static constexpr int INF = 2048;
static constexpr int OUTF = 2048;

static constexpr int BM = 128;
static constexpr int BN = 128;
static constexpr int BK = 64;
static constexpr int LDS = BK + 8;        // 72 fp16 = 144B row stride (conflict-free)
static constexpr int TILE = BM * LDS;     // 9216 elems per tile
static constexpr int STAGES = 3;
static constexpr int STAGE_ELEMS = 2 * TILE;                // A tile + B tile
static constexpr int SMEM_BYTES = STAGES * STAGE_ELEMS * 2; // 110592 B

static constexpr int NTHREADS = 128;

__device__ __half g_A[(size_t)M * K];
__device__ __half g_B[(size_t)N * K];

// ---------------------------------------------------------------------------
// Vectorized prep: 8 elems per thread (two float4 loads -> one uint4 store).
// ---------------------------------------------------------------------------
__global__ void prep_all(const float* __restrict__ xre, const float* __restrict__ xim,
                         const float* __restrict__ wre, const float* __restrict__ wim) {
    size_t idx8 = ((size_t)blockIdx.x * blockDim.x + threadIdx.x) * 8;
    float4 f0, f1;
    float sgn = 1.0f;
    __half* dst;

    if (idx8 < (size_t)M * K) {
        int k = (int)(idx8 & (K - 1));
        int b = (int)(idx8 >> 12);
        const float* src = (k < INF) ? (xre + (size_t)b * INF + k)
                                     : (xim + (size_t)b * INF + (k - INF));
        f0 = *(const float4*)src;
        f1 = *(const float4*)(src + 4);
        dst = g_A + idx8;
    } else {
        size_t j = idx8 - (size_t)M * K;
        int k = (int)(j & (K - 1));
        int n = (int)(j >> 12);
        const float* src;
        if (n < OUTF) {
            if (k < INF) { src = wre + (size_t)n * INF + k; }
            else         { src = wim + (size_t)n * INF + (k - INF); sgn = -1.0f; }
        } else {
            int o = n - OUTF;
            src = (k < INF) ? (wim + (size_t)o * INF + k)
                            : (wre + (size_t)o * INF + (k - INF));
        }
        f0 = *(const float4*)src;
        f1 = *(const float4*)(src + 4);
        dst = g_B + j;
    }

    __half h[8];
    h[0] = __float2half(sgn * f0.x); h[1] = __float2half(sgn * f0.y);
    h[2] = __float2half(sgn * f0.z); h[3] = __float2half(sgn * f0.w);
    h[4] = __float2half(sgn * f1.x); h[5] = __float2half(sgn * f1.y);
    h[6] = __float2half(sgn * f1.z); h[7] = __float2half(sgn * f1.w);
    *(uint4*)dst = *(const uint4*)h;
}

// ---------------------------------------------------------------------------
// helpers
// ---------------------------------------------------------------------------
__device__ __forceinline__ void cp_async16(uint32_t saddr, const void* g) {
    asm volatile("cp.async.cg.shared.global [%0], [%1], 16;" :: "r"(saddr), "l"(g));
}
__device__ __forceinline__ void cp_commit() { asm volatile("cp.async.commit_group;"); }
__device__ __forceinline__ void cp_wait1()  { asm volatile("cp.async.wait_group 1;"); }

__device__ __forceinline__ void ldm_x4(uint32_t* r, uint32_t saddr) {
    asm volatile("ldmatrix.sync.aligned.m8n8.x4.shared.b16 {%0,%1,%2,%3}, [%4];"
                 : "=r"(r[0]), "=r"(r[1]), "=r"(r[2]), "=r"(r[3]) : "r"(saddr));
}
__device__ __forceinline__ void mma16816(float* c, const uint32_t* a, const uint32_t* b) {
    asm volatile("mma.sync.aligned.m16n8k16.row.col.f32.f16.f16.f32 "
                 "{%0,%1,%2,%3}, {%4,%5,%6,%7}, {%8,%9}, {%0,%1,%2,%3};"
                 : "+f"(c[0]), "+f"(c[1]), "+f"(c[2]), "+f"(c[3])
                 : "r"(a[0]), "r"(a[1]), "r"(a[2]), "r"(a[3]),
                   "r"(b[0]), "r"(b[1]));
}

// ---------------------------------------------------------------------------
// GEMM: 128x128 CTA, 4 warps in 2x2, warp tile 64x64, BK=64, 3-stage ring,
// 2 CTAs/SM.
// ---------------------------------------------------------------------------
__global__ void __launch_bounds__(NTHREADS, 2) gemm_f16(float* __restrict__ out) {
    extern __shared__ __align__(16) __half smem[];

    const int tid  = threadIdx.x;
    const int lane = tid & 31;
    const int warp = tid >> 5;
    const int wm = warp >> 1;     // 0..1
    const int wn = warp & 1;      // 0..1
    const int bm0 = blockIdx.y * BM;
    const int bn0 = blockIdx.x * BN;

    float acc[4][8][4];
#pragma unroll
    for (int i = 0; i < 4; i++)
#pragma unroll
        for (int j = 0; j < 8; j++)
#pragma unroll
            for (int q = 0; q < 4; q++) acc[i][j][q] = 0.f;

    // 1024 16B-chunks per tile; 128 threads -> 8 chunks of A and 8 of B each.
    auto load_tile = [&](int st, int k0) {
        __half* sA = smem + st * STAGE_ELEMS;
        __half* sB = sA + TILE;
#pragma unroll
        for (int rep = 0; rep < 8; rep++) {
            int ch  = tid + rep * NTHREADS;   // 0..1023
            int row = ch >> 3;
            int col = (ch & 7) * 8;
            size_t gA = (size_t)(bm0 + row) * K + k0 + col;
            size_t gB = (size_t)(bn0 + row) * K + k0 + col;
            int soff = row * LDS + col;
            cp_async16((uint32_t)__cvta_generic_to_shared(sA + soff), g_A + gA);
            cp_async16((uint32_t)__cvta_generic_to_shared(sB + soff), g_B + gB);
        }
    };

    load_tile(0, 0);       cp_commit();
    load_tile(1, BK);      cp_commit();

    const int NKT = K / BK;   // 64
#pragma unroll 1
    for (int kt = 0; kt < NKT; kt++) {
        cp_wait1();
        __syncthreads();

        if (kt + 2 < NKT) load_tile((kt + 2) % STAGES, (kt + 2) * BK);
        cp_commit();

        const int cur = kt % STAGES;
        const __half* sA = smem + cur * STAGE_ELEMS;
        const __half* sB = sA + TILE;

#pragma unroll
        for (int ks = 0; ks < 4; ks++) {
            const int kk = ks * 16;

            // A: 4 m16 fragments
            uint32_t af[4][4];
            const int arow = wm * 64 + (lane & 15);
            const int acol = kk + ((lane >> 4) << 3);
#pragma unroll
            for (int im = 0; im < 4; im++) {
                int soff = (arow + im * 16) * LDS + acol;
                ldm_x4(af[im], (uint32_t)__cvta_generic_to_shared(sA + soff));
            }

            // B: 8 n8 fragments via 4 x4-ldmatrix
            uint32_t bf[8][2];
            {
                int mset = lane >> 3;
                int nrow_in = (lane & 7) + ((mset >> 1) << 3);
                int col = kk + ((mset & 1) << 3);
#pragma unroll
                for (int ip = 0; ip < 4; ip++) {
                    int nrow = wn * 64 + ip * 16 + nrow_in;
                    int soff = nrow * LDS + col;
                    uint32_t r[4];
                    ldm_x4(r, (uint32_t)__cvta_generic_to_shared(sB + soff));
                    bf[ip * 2][0] = r[0]; bf[ip * 2][1] = r[1];
                    bf[ip * 2 + 1][0] = r[2]; bf[ip * 2 + 1][1] = r[3];
                }
            }

#pragma unroll
            for (int im = 0; im < 4; im++)
#pragma unroll
                for (int in = 0; in < 8; in++) mma16816(acc[im][in], af[im], bf[in]);
        }
        __syncthreads();
    }

    // Epilogue: C[m, n] -> out[m, n & 2047, n >> 11]
    const int gr = lane >> 2;
    const int gc = (lane & 3) << 1;
#pragma unroll
    for (int im = 0; im < 4; im++) {
#pragma unroll
        for (int in = 0; in < 8; in++) {
            int m0 = bm0 + wm * 64 + im * 16 + gr;
            int n0 = bn0 + wn * 64 + in * 8 + gc;
            int c = n0 >> 11;
            int o = n0 & (OUTF - 1);
            out[((size_t)m0 * OUTF + o) * 2 + c]           = acc[im][in][0];
            out[((size_t)m0 * OUTF + o + 1) * 2 + c]       = acc[im][in][1];
            out[((size_t)(m0 + 8) * OUTF + o) * 2 + c]     = acc[im][in][2];
            out[((size_t)(m0 + 8) * OUTF + o + 1) * 2 + c] = acc[im][in][3];
        }
    }
}

// ---------------------------------------------------------------------------
extern "C" void kernel_launch(void* const* d_in, const int* in_sizes, int n_in,
                              void* d_out, int out_size) {
    const float* x_re = (const float*)d_in[0];
    const float* x_im = (const float*)d_in[1];
    const float* w_re = (const float*)d_in[2];
    const float* w_im = (const float*)d_in[3];
    float* out = (float*)d_out;

    cudaFuncSetAttribute(gemm_f16, cudaFuncAttributeMaxDynamicSharedMemorySize,
                         SMEM_BYTES);

    size_t total8 = ((size_t)M * K + (size_t)N * K) / 8;
    prep_all<<<(unsigned)(total8 / 256), 256>>>(x_re, x_im, w_re, w_im);

    dim3 grid(N / BN, M / BM);
    gemm_f16<<<grid, NTHREADS, SMEM_BYTES>>>(out);
}